// round 9
// baseline (speedup 1.0000x reference)
#include <cuda_runtime.h>
#include <cstdint>

// ScoreMatching, sparsity-compacted version.
//  K0 prep: transpose W1,W2,W3,W4 into __device__ scratch (coalesced columns)
//  K1 fwd : 8 samples/CTA, computes h/masks, 0.5||s||^2 -> g_val0,
//           and deterministic ballot-compacted active index lists -> g_idx/g_cnt
//  K2 div : 1 sample/CTA, compacted GEMM chain over active units only:
//           smA = W1[idx1,:] slice ; smB = W2[idx2, idx1] @ smA ;
//           div += sum over idx3 rows of (W3 @ smB) . W4T  (T2 never stored)
//  fp32 throughout, fma.rn.f32x2 packed FMA (128 MAC/cyc/SM).

#define DD   64
#define HH   512
#define DB   16
#define BROW 20          // 16 + 4 pad floats (16B-aligned rows, conflict-poor STS.128)
#define NT   256
#define SPB  8           // samples per forward CTA
#define BMAX 4096

typedef unsigned long long ull;

__device__ float g_W1T[DD * HH];   // W1T[d*512 + i] = W1[i][d]
__device__ float g_W2T[HH * HH];   // W2T[i*512 + j] = W2[j][i]
__device__ float g_W3T[HH * HH];   // W3T[j*512 + k] = W3[k][j]
__device__ float g_W4T[HH * DD];   // W4T[k*64  + d] = W4[d][k]
__device__ float g_val0[BMAX];     // 0.5*||s_b||^2
__device__ int   g_idx[3 * BMAX * HH];
__device__ int   g_cnt[3 * BMAX];

__device__ __forceinline__ ull ffma2(ull a, ull b, ull c) {
    ull d;
    asm("fma.rn.f32x2 %0, %1, %2, %3;" : "=l"(d) : "l"(a), "l"(b), "l"(c));
    return d;
}
__device__ __forceinline__ ull dup2(float w) {
    ull r;
    unsigned int u = __float_as_uint(w);
    asm("mov.b64 %0, {%1, %1};" : "=l"(r) : "r"(u));
    return r;
}
__device__ __forceinline__ float2 unpack2(ull v) {
    unsigned int lo, hi;
    asm("mov.b64 {%0, %1}, %2;" : "=r"(lo), "=r"(hi) : "l"(v));
    return make_float2(__uint_as_float(lo), __uint_as_float(hi));
}

// -------- prep: tiled transposes into __device__ scratch --------
__global__ void prep_transpose(const float* __restrict__ W1,
                               const float* __restrict__ W2,
                               const float* __restrict__ W3,
                               const float* __restrict__ W4) {
    __shared__ float tile[32][33];
    int z = blockIdx.z;
    const float* src = (z == 0) ? W2 : (z == 1) ? W3 : (z == 2) ? W4 : W1;
    float* dst       = (z == 0) ? g_W2T : (z == 1) ? g_W3T : (z == 2) ? g_W4T : g_W1T;
    int R = (z == 2) ? DD : HH;       // source rows
    int C = (z == 3) ? DD : HH;       // source cols
    int c0 = blockIdx.x * 32, r0 = blockIdx.y * 32;
    if (c0 >= C || r0 >= R) return;
    int tx = threadIdx.x, ty = threadIdx.y;
#pragma unroll
    for (int j = ty; j < 32; j += 8)
        tile[j][tx] = src[(size_t)(r0 + j) * C + c0 + tx];
    __syncthreads();
#pragma unroll
    for (int j = ty; j < 32; j += 8)
        dst[(size_t)(c0 + j) * R + r0 + tx] = tile[tx][j];
}

// relu + bias epilogue: 4 packed accumulators -> 8 floats at dst[0..7]
__device__ __forceinline__ void store8(float* dst, const ull* a, float bb) {
#pragma unroll
    for (int q = 0; q < 4; q++) {
        float2 p = unpack2(a[q]);
        float v0 = p.x + bb, v1 = p.y + bb;
        dst[2 * q]     = v0 > 0.f ? v0 : 0.f;
        dst[2 * q + 1] = v1 > 0.f ? v1 : 0.f;
    }
}

// one hidden layer for 8 samples: rows (tid, tid+256), hin layout [k*8+s]
__device__ __forceinline__ void fwd_layer(const float* __restrict__ WT,
                                          const float* __restrict__ bias,
                                          const float* __restrict__ hin,
                                          float* __restrict__ hout, int tid) {
    int r0 = tid, r1 = tid + NT;
    ull a0[4] = {0, 0, 0, 0}, a1[4] = {0, 0, 0, 0};
#pragma unroll 4
    for (int k = 0; k < HH; k++) {
        ull w0 = dup2(WT[(size_t)k * HH + r0]);
        ull w1 = dup2(WT[(size_t)k * HH + r1]);
        const ulonglong2* hp = (const ulonglong2*)(hin + k * SPB);
        ulonglong2 ha = hp[0], hb = hp[1];
        a0[0] = ffma2(w0, ha.x, a0[0]); a0[1] = ffma2(w0, ha.y, a0[1]);
        a0[2] = ffma2(w0, hb.x, a0[2]); a0[3] = ffma2(w0, hb.y, a0[3]);
        a1[0] = ffma2(w1, ha.x, a1[0]); a1[1] = ffma2(w1, ha.y, a1[1]);
        a1[2] = ffma2(w1, hb.x, a1[2]); a1[3] = ffma2(w1, hb.y, a1[3]);
    }
    store8(hout + r0 * SPB, a0, bias[r0]);
    store8(hout + r1 * SPB, a1, bias[r1]);
}

// ------------------------------- K1: forward ---------------------------------
__global__ void __launch_bounds__(NT, 4)
fwd_kernel(const float* __restrict__ x,
           const float* __restrict__ b1, const float* __restrict__ b2,
           const float* __restrict__ b3,
           const float* __restrict__ W4, const float* __restrict__ b4,
           int B) {
    extern __shared__ float sm[];
    float* xs   = sm;                   // 64*8
    float* sh1  = xs + DD * SPB;        // 512*8
    float* sh2  = sh1 + HH * SPB;
    float* sh3  = sh2 + HH * SPB;
    float* red2 = sh3 + HH * SPB;       // 16

    const int tid = threadIdx.x, lane = tid & 31, wid = tid >> 5;
    const int b0 = blockIdx.x * SPB;

    for (int t = tid; t < DD * SPB; t += NT) {
        int s = t >> 6, d = t & 63;
        int b = b0 + s;
        xs[d * SPB + s] = (b < B) ? x[(size_t)b * DD + d] : 0.f;
    }
    __syncthreads();

    // layer 1 (via W1T, coalesced)
    {
        int r0 = tid, r1 = tid + NT;
        ull a0[4] = {0, 0, 0, 0}, a1[4] = {0, 0, 0, 0};
#pragma unroll 8
        for (int d = 0; d < DD; d++) {
            ull w0 = dup2(g_W1T[d * HH + r0]);
            ull w1 = dup2(g_W1T[d * HH + r1]);
            const ulonglong2* xp = (const ulonglong2*)(xs + d * SPB);
            ulonglong2 xa = xp[0], xb = xp[1];
            a0[0] = ffma2(w0, xa.x, a0[0]); a0[1] = ffma2(w0, xa.y, a0[1]);
            a0[2] = ffma2(w0, xb.x, a0[2]); a0[3] = ffma2(w0, xb.y, a0[3]);
            a1[0] = ffma2(w1, xa.x, a1[0]); a1[1] = ffma2(w1, xa.y, a1[1]);
            a1[2] = ffma2(w1, xb.x, a1[2]); a1[3] = ffma2(w1, xb.y, a1[3]);
        }
        store8(sh1 + r0 * SPB, a0, b1[r0]);
        store8(sh1 + r1 * SPB, a1, b1[r1]);
    }
    __syncthreads();
    fwd_layer(g_W2T, b2, sh1, sh2, tid);
    __syncthreads();
    fwd_layer(g_W3T, b3, sh2, sh3, tid);
    __syncthreads();

    // s = W4 h3 + b4 ; accumulate 0.5 s^2 (two task passes per thread)
    float sum0 = 0.f, sum1 = 0.f;
#pragma unroll
    for (int pass = 0; pass < 2; pass++) {
        int id = tid + pass * NT;
        int d = id & 63, smp = id >> 6;
        const float4* wrow = (const float4*)(W4 + (size_t)d * HH);
        float acc = 0.f;
#pragma unroll 4
        for (int q = 0; q < HH / 4; q++) {
            float4 w = wrow[q];
            acc = fmaf(w.x, sh3[(4 * q + 0) * SPB + smp], acc);
            acc = fmaf(w.y, sh3[(4 * q + 1) * SPB + smp], acc);
            acc = fmaf(w.z, sh3[(4 * q + 2) * SPB + smp], acc);
            acc = fmaf(w.w, sh3[(4 * q + 3) * SPB + smp], acc);
        }
        float s = acc + b4[d];
        if (pass == 0) sum0 = 0.5f * s * s; else sum1 = 0.5f * s * s;
    }
#pragma unroll
    for (int off = 16; off; off >>= 1) {
        sum0 += __shfl_down_sync(0xffffffffu, sum0, off);
        sum1 += __shfl_down_sync(0xffffffffu, sum1, off);
    }
    if (lane == 0) { red2[wid] = sum0; red2[8 + wid] = sum1; }
    __syncthreads();
    if (tid < SPB && b0 + tid < B) {
        int smp = tid;
        float v = (smp < 4) ? red2[2 * smp] + red2[2 * smp + 1]
                            : red2[8 + 2 * (smp - 4)] + red2[8 + 2 * (smp - 4) + 1];
        g_val0[b0 + smp] = v;
    }

    // deterministic ballot compaction: warp w handles sample w, 3 lists
    if (wid < SPB && b0 + wid < B) {
        int b = b0 + wid;
        const float* hs0 = sh1;
        const float* hs1 = sh2;
        const float* hs2 = sh3;
        for (int l = 0; l < 3; l++) {
            const float* h = (l == 0) ? hs0 : (l == 1) ? hs1 : hs2;
            int* gi = g_idx + ((size_t)l * BMAX + b) * HH;
            int base = 0;
#pragma unroll
            for (int c = 0; c < 16; c++) {
                int e = c * 32 + lane;
                bool f = h[e * SPB + wid] > 0.f;   // h>0 <=> a>0 (strict, torch-style)
                unsigned bal = __ballot_sync(0xffffffffu, f);
                int pos = base + __popc(bal & ((1u << lane) - 1u));
                if (f) gi[pos] = e;
                base += __popc(bal);
            }
            for (int e = base + lane; e < HH; e += 32) gi[e] = 0;  // pad -> zeroed rows
            if (lane == 0) g_cnt[l * BMAX + b] = base;
        }
    }
}

// ------------------------------ K2: divergence --------------------------------
__global__ void __launch_bounds__(NT, 2)
div_kernel(const float* __restrict__ W1, float* __restrict__ out, int B) {
    extern __shared__ float sm[];
    int*   idx1 = (int*)sm;              // 512
    int*   idx2 = idx1 + HH;
    int*   idx3 = idx2 + HH;
    float* red  = (float*)(idx3 + HH);   // 8
    float* smA  = red + 8;               // 512*20 (byte offset 6176, 16B aligned)
    float* smB  = smA + HH * BROW;

    const int tid = threadIdx.x;
    const int b = blockIdx.x;

    const int n1 = g_cnt[b], n2 = g_cnt[BMAX + b], n3 = g_cnt[2 * BMAX + b];
    for (int e = tid; e < HH; e += NT) {
        idx1[e] = g_idx[(size_t)b * HH + e];
        idx2[e] = g_idx[((size_t)BMAX + b) * HH + e];
        idx3[e] = g_idx[((size_t)2 * BMAX + b) * HH + e];
    }
    __syncthreads();

    const int n1p = (n1 + 3) & ~3;
    const int n2p = (n2 + 3) & ~3;
    float div_acc = 0.f;

#pragma unroll 1
    for (int d0 = 0; d0 < DD; d0 += DB) {
        // stage smA[ic][0..15] = W1[idx1[ic]][d0..d0+15]; zero pad rows
        for (int ic = tid; ic < n1p; ic += NT) {
            float4 v0, v1, v2, v3;
            if (ic < n1) {
                const float4* src = (const float4*)(W1 + (size_t)idx1[ic] * DD + d0);
                v0 = src[0]; v1 = src[1]; v2 = src[2]; v3 = src[3];
            } else {
                v0 = v1 = v2 = v3 = make_float4(0.f, 0.f, 0.f, 0.f);
            }
            float4* dst = (float4*)(smA + ic * BROW);
            dst[0] = v0; dst[1] = v1; dst[2] = v2; dst[3] = v3;
        }
        __syncthreads();

        // GEMM1: smB[jc] = sum_ic W2[idx2[jc], idx1[ic]] * smA[ic]
        for (int jc = tid; jc < n2p; jc += NT) {
            float4 o0, o1, o2, o3;
            if (jc < n2) {
                const float* wcol = g_W2T + idx2[jc];
                ull acc[8];
#pragma unroll
                for (int q = 0; q < 8; q++) acc[q] = 0ull;
#pragma unroll 4
                for (int ic = 0; ic < n1p; ic++) {
                    ull wd = dup2(wcol[(size_t)idx1[ic] * HH]);
                    const ulonglong2* br = (const ulonglong2*)(smA + ic * BROW);
                    ulonglong2 u0 = br[0], u1 = br[1], u2 = br[2], u3 = br[3];
                    acc[0] = ffma2(wd, u0.x, acc[0]); acc[1] = ffma2(wd, u0.y, acc[1]);
                    acc[2] = ffma2(wd, u1.x, acc[2]); acc[3] = ffma2(wd, u1.y, acc[3]);
                    acc[4] = ffma2(wd, u2.x, acc[4]); acc[5] = ffma2(wd, u2.y, acc[5]);
                    acc[6] = ffma2(wd, u3.x, acc[6]); acc[7] = ffma2(wd, u3.y, acc[7]);
                }
                float2 p0 = unpack2(acc[0]), p1 = unpack2(acc[1]);
                float2 p2 = unpack2(acc[2]), p3 = unpack2(acc[3]);
                float2 p4 = unpack2(acc[4]), p5 = unpack2(acc[5]);
                float2 p6 = unpack2(acc[6]), p7 = unpack2(acc[7]);
                o0 = make_float4(p0.x, p0.y, p1.x, p1.y);
                o1 = make_float4(p2.x, p2.y, p3.x, p3.y);
                o2 = make_float4(p4.x, p4.y, p5.x, p5.y);
                o3 = make_float4(p6.x, p6.y, p7.x, p7.y);
            } else {
                o0 = o1 = o2 = o3 = make_float4(0.f, 0.f, 0.f, 0.f);
            }
            float4* dst = (float4*)(smB + jc * BROW);
            dst[0] = o0; dst[1] = o1; dst[2] = o2; dst[3] = o3;
        }
        __syncthreads();

        // GEMM2 + fold: for active k rows, dot (W3 @ smB)[k] with W4T[k, d0..]
        for (int kc = tid; kc < n3; kc += NT) {
            int k = idx3[kc];
            const float* wcol = g_W3T + k;
            ull acc[8];
#pragma unroll
            for (int q = 0; q < 8; q++) acc[q] = 0ull;
#pragma unroll 4
            for (int jc = 0; jc < n2p; jc++) {
                ull wd = dup2(wcol[(size_t)idx2[jc] * HH]);
                const ulonglong2* br = (const ulonglong2*)(smB + jc * BROW);
                ulonglong2 u0 = br[0], u1 = br[1], u2 = br[2], u3 = br[3];
                acc[0] = ffma2(wd, u0.x, acc[0]); acc[1] = ffma2(wd, u0.y, acc[1]);
                acc[2] = ffma2(wd, u1.x, acc[2]); acc[3] = ffma2(wd, u1.y, acc[3]);
                acc[4] = ffma2(wd, u2.x, acc[4]); acc[5] = ffma2(wd, u2.y, acc[5]);
                acc[6] = ffma2(wd, u3.x, acc[6]); acc[7] = ffma2(wd, u3.y, acc[7]);
            }
            const float4* w4 = (const float4*)(g_W4T + (size_t)k * DD + d0);
            float4 wa = w4[0], wb = w4[1], wc = w4[2], wd4 = w4[3];
            float2 p0 = unpack2(acc[0]), p1 = unpack2(acc[1]);
            float2 p2 = unpack2(acc[2]), p3 = unpack2(acc[3]);
            float2 p4 = unpack2(acc[4]), p5 = unpack2(acc[5]);
            float2 p6 = unpack2(acc[6]), p7 = unpack2(acc[7]);
            div_acc += p0.x * wa.x + p0.y * wa.y + p1.x * wa.z + p1.y * wa.w
                     + p2.x * wb.x + p2.y * wb.y + p3.x * wb.z + p3.y * wb.w
                     + p4.x * wc.x + p4.y * wc.y + p5.x * wc.z + p5.y * wc.w
                     + p6.x * wd4.x + p6.y * wd4.y + p7.x * wd4.z + p7.y * wd4.w;
        }
        __syncthreads();
    }

    float v = div_acc;
#pragma unroll
    for (int off = 16; off; off >>= 1) v += __shfl_down_sync(0xffffffffu, v, off);
    if ((tid & 31) == 0) red[tid >> 5] = v;
    __syncthreads();
    if (tid == 0) {
        float t = g_val0[b];
#pragma unroll
        for (int w = 0; w < NT / 32; w++) t += red[w];
        out[b] = t;
    }
}

// ------------------------------- launcher -----------------------------------
extern "C" void kernel_launch(void* const* d_in, const int* in_sizes, int n_in,
                              void* d_out, int out_size) {
    const float* x  = (const float*)d_in[0];
    const float* W1 = (const float*)d_in[1];
    const float* b1 = (const float*)d_in[2];
    const float* W2 = (const float*)d_in[3];
    const float* b2 = (const float*)d_in[4];
    const float* W3 = (const float*)d_in[5];
    const float* b3 = (const float*)d_in[6];
    const float* W4 = (const float*)d_in[7];
    const float* b4 = (const float*)d_in[8];
    float* out = (float*)d_out;

    int B = in_sizes[0] / DD;

    prep_transpose<<<dim3(16, 16, 4), dim3(32, 8)>>>(W1, W2, W3, W4);

    size_t sm1 = (size_t)(DD * SPB + 3 * HH * SPB + 16) * sizeof(float);
    cudaFuncSetAttribute(fwd_kernel, cudaFuncAttributeMaxDynamicSharedMemorySize, (int)sm1);
    fwd_kernel<<<(B + SPB - 1) / SPB, NT, sm1>>>(x, b1, b2, b3, W4, b4, B);

    size_t sm2 = (size_t)(3 * HH) * sizeof(int) + (size_t)(8 + 2 * HH * BROW) * sizeof(float);
    cudaFuncSetAttribute(div_kernel, cudaFuncAttributeMaxDynamicSharedMemorySize, (int)sm2);
    div_kernel<<<B, NT, sm2>>>(W1, out, B);
}

// round 10
// speedup vs baseline: 1.0013x; 1.0013x over previous
#include <cuda_runtime.h>
#include <cstdint>

// ScoreMatching, sparsity-compacted version.
//  K0 prep: transpose W1,W2,W3,W4 into __device__ scratch (coalesced columns)
//  K1 fwd : 8 samples/CTA, computes h/masks, 0.5||s||^2 -> g_val0,
//           and deterministic ballot-compacted active index lists -> g_idx/g_cnt
//  K2 div : 1 sample/CTA, compacted GEMM chain over active units only:
//           smA = W1[idx1,:] slice ; smB = W2[idx2, idx1] @ smA ;
//           div += sum over idx3 rows of (W3 @ smB) . W4T  (T2 never stored)
//  fp32 throughout, fma.rn.f32x2 packed FMA (128 MAC/cyc/SM).

#define DD   64
#define HH   512
#define DB   16
#define BROW 20          // 16 + 4 pad floats (16B-aligned rows, conflict-poor STS.128)
#define NT   256
#define SPB  8           // samples per forward CTA
#define BMAX 4096

typedef unsigned long long ull;

__device__ float g_W1T[DD * HH];   // W1T[d*512 + i] = W1[i][d]
__device__ float g_W2T[HH * HH];   // W2T[i*512 + j] = W2[j][i]
__device__ float g_W3T[HH * HH];   // W3T[j*512 + k] = W3[k][j]
__device__ float g_W4T[HH * DD];   // W4T[k*64  + d] = W4[d][k]
__device__ float g_val0[BMAX];     // 0.5*||s_b||^2
__device__ int   g_idx[3 * BMAX * HH];
__device__ int   g_cnt[3 * BMAX];

__device__ __forceinline__ ull ffma2(ull a, ull b, ull c) {
    ull d;
    asm("fma.rn.f32x2 %0, %1, %2, %3;" : "=l"(d) : "l"(a), "l"(b), "l"(c));
    return d;
}
__device__ __forceinline__ ull dup2(float w) {
    ull r;
    unsigned int u = __float_as_uint(w);
    asm("mov.b64 %0, {%1, %1};" : "=l"(r) : "r"(u));
    return r;
}
__device__ __forceinline__ float2 unpack2(ull v) {
    unsigned int lo, hi;
    asm("mov.b64 {%0, %1}, %2;" : "=r"(lo), "=r"(hi) : "l"(v));
    return make_float2(__uint_as_float(lo), __uint_as_float(hi));
}

// -------- prep: tiled transposes into __device__ scratch --------
__global__ void prep_transpose(const float* __restrict__ W1,
                               const float* __restrict__ W2,
                               const float* __restrict__ W3,
                               const float* __restrict__ W4) {
    __shared__ float tile[32][33];
    int z = blockIdx.z;
    const float* src = (z == 0) ? W2 : (z == 1) ? W3 : (z == 2) ? W4 : W1;
    float* dst       = (z == 0) ? g_W2T : (z == 1) ? g_W3T : (z == 2) ? g_W4T : g_W1T;
    int R = (z == 2) ? DD : HH;       // source rows
    int C = (z == 3) ? DD : HH;       // source cols
    int c0 = blockIdx.x * 32, r0 = blockIdx.y * 32;
    if (c0 >= C || r0 >= R) return;
    int tx = threadIdx.x, ty = threadIdx.y;
#pragma unroll
    for (int j = ty; j < 32; j += 8)
        tile[j][tx] = src[(size_t)(r0 + j) * C + c0 + tx];
    __syncthreads();
#pragma unroll
    for (int j = ty; j < 32; j += 8)
        dst[(size_t)(c0 + j) * R + r0 + tx] = tile[tx][j];
}

// relu + bias epilogue: 4 packed accumulators -> 8 floats at dst[0..7]
__device__ __forceinline__ void store8(float* dst, const ull* a, float bb) {
#pragma unroll
    for (int q = 0; q < 4; q++) {
        float2 p = unpack2(a[q]);
        float v0 = p.x + bb, v1 = p.y + bb;
        dst[2 * q]     = v0 > 0.f ? v0 : 0.f;
        dst[2 * q + 1] = v1 > 0.f ? v1 : 0.f;
    }
}

// one hidden layer for 8 samples: rows (tid, tid+256), hin layout [k*8+s]
__device__ __forceinline__ void fwd_layer(const float* __restrict__ WT,
                                          const float* __restrict__ bias,
                                          const float* __restrict__ hin,
                                          float* __restrict__ hout, int tid) {
    int r0 = tid, r1 = tid + NT;
    ull a0[4] = {0, 0, 0, 0}, a1[4] = {0, 0, 0, 0};
#pragma unroll 4
    for (int k = 0; k < HH; k++) {
        ull w0 = dup2(WT[(size_t)k * HH + r0]);
        ull w1 = dup2(WT[(size_t)k * HH + r1]);
        const ulonglong2* hp = (const ulonglong2*)(hin + k * SPB);
        ulonglong2 ha = hp[0], hb = hp[1];
        a0[0] = ffma2(w0, ha.x, a0[0]); a0[1] = ffma2(w0, ha.y, a0[1]);
        a0[2] = ffma2(w0, hb.x, a0[2]); a0[3] = ffma2(w0, hb.y, a0[3]);
        a1[0] = ffma2(w1, ha.x, a1[0]); a1[1] = ffma2(w1, ha.y, a1[1]);
        a1[2] = ffma2(w1, hb.x, a1[2]); a1[3] = ffma2(w1, hb.y, a1[3]);
    }
    store8(hout + r0 * SPB, a0, bias[r0]);
    store8(hout + r1 * SPB, a1, bias[r1]);
}

// ------------------------------- K1: forward ---------------------------------
__global__ void __launch_bounds__(NT, 4)
fwd_kernel(const float* __restrict__ x,
           const float* __restrict__ b1, const float* __restrict__ b2,
           const float* __restrict__ b3,
           const float* __restrict__ W4, const float* __restrict__ b4,
           int B) {
    extern __shared__ float sm[];
    float* xs   = sm;                   // 64*8
    float* sh1  = xs + DD * SPB;        // 512*8
    float* sh2  = sh1 + HH * SPB;
    float* sh3  = sh2 + HH * SPB;
    float* red2 = sh3 + HH * SPB;       // 16

    const int tid = threadIdx.x, lane = tid & 31, wid = tid >> 5;
    const int b0 = blockIdx.x * SPB;

    for (int t = tid; t < DD * SPB; t += NT) {
        int s = t >> 6, d = t & 63;
        int b = b0 + s;
        xs[d * SPB + s] = (b < B) ? x[(size_t)b * DD + d] : 0.f;
    }
    __syncthreads();

    // layer 1 (via W1T, coalesced)
    {
        int r0 = tid, r1 = tid + NT;
        ull a0[4] = {0, 0, 0, 0}, a1[4] = {0, 0, 0, 0};
#pragma unroll 8
        for (int d = 0; d < DD; d++) {
            ull w0 = dup2(g_W1T[d * HH + r0]);
            ull w1 = dup2(g_W1T[d * HH + r1]);
            const ulonglong2* xp = (const ulonglong2*)(xs + d * SPB);
            ulonglong2 xa = xp[0], xb = xp[1];
            a0[0] = ffma2(w0, xa.x, a0[0]); a0[1] = ffma2(w0, xa.y, a0[1]);
            a0[2] = ffma2(w0, xb.x, a0[2]); a0[3] = ffma2(w0, xb.y, a0[3]);
            a1[0] = ffma2(w1, xa.x, a1[0]); a1[1] = ffma2(w1, xa.y, a1[1]);
            a1[2] = ffma2(w1, xb.x, a1[2]); a1[3] = ffma2(w1, xb.y, a1[3]);
        }
        store8(sh1 + r0 * SPB, a0, b1[r0]);
        store8(sh1 + r1 * SPB, a1, b1[r1]);
    }
    __syncthreads();
    fwd_layer(g_W2T, b2, sh1, sh2, tid);
    __syncthreads();
    fwd_layer(g_W3T, b3, sh2, sh3, tid);
    __syncthreads();

    // s = W4 h3 + b4 ; accumulate 0.5 s^2 (two task passes per thread)
    float sum0 = 0.f, sum1 = 0.f;
#pragma unroll
    for (int pass = 0; pass < 2; pass++) {
        int id = tid + pass * NT;
        int d = id & 63, smp = id >> 6;
        const float4* wrow = (const float4*)(W4 + (size_t)d * HH);
        float acc = 0.f;
#pragma unroll 4
        for (int q = 0; q < HH / 4; q++) {
            float4 w = wrow[q];
            acc = fmaf(w.x, sh3[(4 * q + 0) * SPB + smp], acc);
            acc = fmaf(w.y, sh3[(4 * q + 1) * SPB + smp], acc);
            acc = fmaf(w.z, sh3[(4 * q + 2) * SPB + smp], acc);
            acc = fmaf(w.w, sh3[(4 * q + 3) * SPB + smp], acc);
        }
        float s = acc + b4[d];
        if (pass == 0) sum0 = 0.5f * s * s; else sum1 = 0.5f * s * s;
    }
#pragma unroll
    for (int off = 16; off; off >>= 1) {
        sum0 += __shfl_down_sync(0xffffffffu, sum0, off);
        sum1 += __shfl_down_sync(0xffffffffu, sum1, off);
    }
    if (lane == 0) { red2[wid] = sum0; red2[8 + wid] = sum1; }
    __syncthreads();
    if (tid < SPB && b0 + tid < B) {
        int smp = tid;
        float v = (smp < 4) ? red2[2 * smp] + red2[2 * smp + 1]
                            : red2[8 + 2 * (smp - 4)] + red2[8 + 2 * (smp - 4) + 1];
        g_val0[b0 + smp] = v;
    }

    // deterministic ballot compaction: warp w handles sample w, 3 lists
    if (wid < SPB && b0 + wid < B) {
        int b = b0 + wid;
        const float* hs0 = sh1;
        const float* hs1 = sh2;
        const float* hs2 = sh3;
        for (int l = 0; l < 3; l++) {
            const float* h = (l == 0) ? hs0 : (l == 1) ? hs1 : hs2;
            int* gi = g_idx + ((size_t)l * BMAX + b) * HH;
            int base = 0;
#pragma unroll
            for (int c = 0; c < 16; c++) {
                int e = c * 32 + lane;
                bool f = h[e * SPB + wid] > 0.f;   // h>0 <=> a>0 (strict, torch-style)
                unsigned bal = __ballot_sync(0xffffffffu, f);
                int pos = base + __popc(bal & ((1u << lane) - 1u));
                if (f) gi[pos] = e;
                base += __popc(bal);
            }
            for (int e = base + lane; e < HH; e += 32) gi[e] = 0;  // pad -> zeroed rows
            if (lane == 0) g_cnt[l * BMAX + b] = base;
        }
    }
}

// ------------------------------ K2: divergence --------------------------------
__global__ void __launch_bounds__(NT, 2)
div_kernel(const float* __restrict__ W1, float* __restrict__ out, int B) {
    extern __shared__ float sm[];
    int*   idx1 = (int*)sm;              // 512
    int*   idx2 = idx1 + HH;
    int*   idx3 = idx2 + HH;
    float* red  = (float*)(idx3 + HH);   // 8
    float* smA  = red + 8;               // 512*20 (byte offset 6176, 16B aligned)
    float* smB  = smA + HH * BROW;

    const int tid = threadIdx.x;
    const int b = blockIdx.x;

    const int n1 = g_cnt[b], n2 = g_cnt[BMAX + b], n3 = g_cnt[2 * BMAX + b];
    for (int e = tid; e < HH; e += NT) {
        idx1[e] = g_idx[(size_t)b * HH + e];
        idx2[e] = g_idx[((size_t)BMAX + b) * HH + e];
        idx3[e] = g_idx[((size_t)2 * BMAX + b) * HH + e];
    }
    __syncthreads();

    const int n1p = (n1 + 3) & ~3;
    const int n2p = (n2 + 3) & ~3;
    float div_acc = 0.f;

#pragma unroll 1
    for (int d0 = 0; d0 < DD; d0 += DB) {
        // stage smA[ic][0..15] = W1[idx1[ic]][d0..d0+15]; zero pad rows
        for (int ic = tid; ic < n1p; ic += NT) {
            float4 v0, v1, v2, v3;
            if (ic < n1) {
                const float4* src = (const float4*)(W1 + (size_t)idx1[ic] * DD + d0);
                v0 = src[0]; v1 = src[1]; v2 = src[2]; v3 = src[3];
            } else {
                v0 = v1 = v2 = v3 = make_float4(0.f, 0.f, 0.f, 0.f);
            }
            float4* dst = (float4*)(smA + ic * BROW);
            dst[0] = v0; dst[1] = v1; dst[2] = v2; dst[3] = v3;
        }
        __syncthreads();

        // GEMM1: smB[jc] = sum_ic W2[idx2[jc], idx1[ic]] * smA[ic]
        for (int jc = tid; jc < n2p; jc += NT) {
            float4 o0, o1, o2, o3;
            if (jc < n2) {
                const float* wcol = g_W2T + idx2[jc];
                ull acc[8];
#pragma unroll
                for (int q = 0; q < 8; q++) acc[q] = 0ull;
#pragma unroll 4
                for (int ic = 0; ic < n1p; ic++) {
                    ull wd = dup2(wcol[(size_t)idx1[ic] * HH]);
                    const ulonglong2* br = (const ulonglong2*)(smA + ic * BROW);
                    ulonglong2 u0 = br[0], u1 = br[1], u2 = br[2], u3 = br[3];
                    acc[0] = ffma2(wd, u0.x, acc[0]); acc[1] = ffma2(wd, u0.y, acc[1]);
                    acc[2] = ffma2(wd, u1.x, acc[2]); acc[3] = ffma2(wd, u1.y, acc[3]);
                    acc[4] = ffma2(wd, u2.x, acc[4]); acc[5] = ffma2(wd, u2.y, acc[5]);
                    acc[6] = ffma2(wd, u3.x, acc[6]); acc[7] = ffma2(wd, u3.y, acc[7]);
                }
                float2 p0 = unpack2(acc[0]), p1 = unpack2(acc[1]);
                float2 p2 = unpack2(acc[2]), p3 = unpack2(acc[3]);
                float2 p4 = unpack2(acc[4]), p5 = unpack2(acc[5]);
                float2 p6 = unpack2(acc[6]), p7 = unpack2(acc[7]);
                o0 = make_float4(p0.x, p0.y, p1.x, p1.y);
                o1 = make_float4(p2.x, p2.y, p3.x, p3.y);
                o2 = make_float4(p4.x, p4.y, p5.x, p5.y);
                o3 = make_float4(p6.x, p6.y, p7.x, p7.y);
            } else {
                o0 = o1 = o2 = o3 = make_float4(0.f, 0.f, 0.f, 0.f);
            }
            float4* dst = (float4*)(smB + jc * BROW);
            dst[0] = o0; dst[1] = o1; dst[2] = o2; dst[3] = o3;
        }
        __syncthreads();

        // GEMM2 + fold: for active k rows, dot (W3 @ smB)[k] with W4T[k, d0..]
        for (int kc = tid; kc < n3; kc += NT) {
            int k = idx3[kc];
            const float* wcol = g_W3T + k;
            ull acc[8];
#pragma unroll
            for (int q = 0; q < 8; q++) acc[q] = 0ull;
#pragma unroll 4
            for (int jc = 0; jc < n2p; jc++) {
                ull wd = dup2(wcol[(size_t)idx2[jc] * HH]);
                const ulonglong2* br = (const ulonglong2*)(smB + jc * BROW);
                ulonglong2 u0 = br[0], u1 = br[1], u2 = br[2], u3 = br[3];
                acc[0] = ffma2(wd, u0.x, acc[0]); acc[1] = ffma2(wd, u0.y, acc[1]);
                acc[2] = ffma2(wd, u1.x, acc[2]); acc[3] = ffma2(wd, u1.y, acc[3]);
                acc[4] = ffma2(wd, u2.x, acc[4]); acc[5] = ffma2(wd, u2.y, acc[5]);
                acc[6] = ffma2(wd, u3.x, acc[6]); acc[7] = ffma2(wd, u3.y, acc[7]);
            }
            const float4* w4 = (const float4*)(g_W4T + (size_t)k * DD + d0);
            float4 wa = w4[0], wb = w4[1], wc = w4[2], wd4 = w4[3];
            float2 p0 = unpack2(acc[0]), p1 = unpack2(acc[1]);
            float2 p2 = unpack2(acc[2]), p3 = unpack2(acc[3]);
            float2 p4 = unpack2(acc[4]), p5 = unpack2(acc[5]);
            float2 p6 = unpack2(acc[6]), p7 = unpack2(acc[7]);
            div_acc += p0.x * wa.x + p0.y * wa.y + p1.x * wa.z + p1.y * wa.w
                     + p2.x * wb.x + p2.y * wb.y + p3.x * wb.z + p3.y * wb.w
                     + p4.x * wc.x + p4.y * wc.y + p5.x * wc.z + p5.y * wc.w
                     + p6.x * wd4.x + p6.y * wd4.y + p7.x * wd4.z + p7.y * wd4.w;
        }
        __syncthreads();
    }

    float v = div_acc;
#pragma unroll
    for (int off = 16; off; off >>= 1) v += __shfl_down_sync(0xffffffffu, v, off);
    if ((tid & 31) == 0) red[tid >> 5] = v;
    __syncthreads();
    if (tid == 0) {
        float t = g_val0[b];
#pragma unroll
        for (int w = 0; w < NT / 32; w++) t += red[w];
        out[b] = t;
    }
}

// ------------------------------- launcher -----------------------------------
extern "C" void kernel_launch(void* const* d_in, const int* in_sizes, int n_in,
                              void* d_out, int out_size) {
    const float* x  = (const float*)d_in[0];
    const float* W1 = (const float*)d_in[1];
    const float* b1 = (const float*)d_in[2];
    const float* W2 = (const float*)d_in[3];
    const float* b2 = (const float*)d_in[4];
    const float* W3 = (const float*)d_in[5];
    const float* b3 = (const float*)d_in[6];
    const float* W4 = (const float*)d_in[7];
    const float* b4 = (const float*)d_in[8];
    float* out = (float*)d_out;

    int B = in_sizes[0] / DD;

    prep_transpose<<<dim3(16, 16, 4), dim3(32, 8)>>>(W1, W2, W3, W4);

    size_t sm1 = (size_t)(DD * SPB + 3 * HH * SPB + 16) * sizeof(float);
    cudaFuncSetAttribute(fwd_kernel, cudaFuncAttributeMaxDynamicSharedMemorySize, (int)sm1);
    fwd_kernel<<<(B + SPB - 1) / SPB, NT, sm1>>>(x, b1, b2, b3, W4, b4, B);

    size_t sm2 = (size_t)(3 * HH) * sizeof(int) + (size_t)(8 + 2 * HH * BROW) * sizeof(float);
    cudaFuncSetAttribute(div_kernel, cudaFuncAttributeMaxDynamicSharedMemorySize, (int)sm2);
    div_kernel<<<B, NT, sm2>>>(W1, out, B);
}

// round 11
// speedup vs baseline: 1.0036x; 1.0024x over previous
#include <cuda_runtime.h>
#include <cstdint>

// ScoreMatching, sparsity-compacted version.
//  K0 prep: transpose W1,W2,W3,W4 into __device__ scratch (coalesced columns)
//  K1 fwd : 8 samples/CTA, computes h/masks, 0.5||s||^2 -> g_val0,
//           and deterministic ballot-compacted active index lists -> g_idx/g_cnt
//  K2 div : 1 sample/CTA, compacted GEMM chain over active units only:
//           smA = W1[idx1,:] slice ; smB = W2[idx2, idx1] @ smA ;
//           div += sum over idx3 rows of (W3 @ smB) . W4T  (T2 never stored)
//  fp32 throughout, fma.rn.f32x2 packed FMA (128 MAC/cyc/SM).

#define DD   64
#define HH   512
#define DB   16
#define BROW 20          // 16 + 4 pad floats (16B-aligned rows, conflict-poor STS.128)
#define NT   256
#define SPB  8           // samples per forward CTA
#define BMAX 4096

typedef unsigned long long ull;

__device__ float g_W1T[DD * HH];   // W1T[d*512 + i] = W1[i][d]
__device__ float g_W2T[HH * HH];   // W2T[i*512 + j] = W2[j][i]
__device__ float g_W3T[HH * HH];   // W3T[j*512 + k] = W3[k][j]
__device__ float g_W4T[HH * DD];   // W4T[k*64  + d] = W4[d][k]
__device__ float g_val0[BMAX];     // 0.5*||s_b||^2
__device__ int   g_idx[3 * BMAX * HH];
__device__ int   g_cnt[3 * BMAX];

__device__ __forceinline__ ull ffma2(ull a, ull b, ull c) {
    ull d;
    asm("fma.rn.f32x2 %0, %1, %2, %3;" : "=l"(d) : "l"(a), "l"(b), "l"(c));
    return d;
}
__device__ __forceinline__ ull dup2(float w) {
    ull r;
    unsigned int u = __float_as_uint(w);
    asm("mov.b64 %0, {%1, %1};" : "=l"(r) : "r"(u));
    return r;
}
__device__ __forceinline__ float2 unpack2(ull v) {
    unsigned int lo, hi;
    asm("mov.b64 {%0, %1}, %2;" : "=r"(lo), "=r"(hi) : "l"(v));
    return make_float2(__uint_as_float(lo), __uint_as_float(hi));
}

// -------- prep: tiled transposes into __device__ scratch --------
__global__ void prep_transpose(const float* __restrict__ W1,
                               const float* __restrict__ W2,
                               const float* __restrict__ W3,
                               const float* __restrict__ W4) {
    __shared__ float tile[32][33];
    int z = blockIdx.z;
    const float* src = (z == 0) ? W2 : (z == 1) ? W3 : (z == 2) ? W4 : W1;
    float* dst       = (z == 0) ? g_W2T : (z == 1) ? g_W3T : (z == 2) ? g_W4T : g_W1T;
    int R = (z == 2) ? DD : HH;       // source rows
    int C = (z == 3) ? DD : HH;       // source cols
    int c0 = blockIdx.x * 32, r0 = blockIdx.y * 32;
    if (c0 >= C || r0 >= R) return;
    int tx = threadIdx.x, ty = threadIdx.y;
#pragma unroll
    for (int j = ty; j < 32; j += 8)
        tile[j][tx] = src[(size_t)(r0 + j) * C + c0 + tx];
    __syncthreads();
#pragma unroll
    for (int j = ty; j < 32; j += 8)
        dst[(size_t)(c0 + j) * R + r0 + tx] = tile[tx][j];
}

// relu + bias epilogue: 4 packed accumulators -> 8 floats at dst[0..7]
__device__ __forceinline__ void store8(float* dst, const ull* a, float bb) {
#pragma unroll
    for (int q = 0; q < 4; q++) {
        float2 p = unpack2(a[q]);
        float v0 = p.x + bb, v1 = p.y + bb;
        dst[2 * q]     = v0 > 0.f ? v0 : 0.f;
        dst[2 * q + 1] = v1 > 0.f ? v1 : 0.f;
    }
}

// one hidden layer for 8 samples: rows (tid, tid+256), hin layout [k*8+s]
__device__ __forceinline__ void fwd_layer(const float* __restrict__ WT,
                                          const float* __restrict__ bias,
                                          const float* __restrict__ hin,
                                          float* __restrict__ hout, int tid) {
    int r0 = tid, r1 = tid + NT;
    ull a0[4] = {0, 0, 0, 0}, a1[4] = {0, 0, 0, 0};
#pragma unroll 4
    for (int k = 0; k < HH; k++) {
        ull w0 = dup2(WT[(size_t)k * HH + r0]);
        ull w1 = dup2(WT[(size_t)k * HH + r1]);
        const ulonglong2* hp = (const ulonglong2*)(hin + k * SPB);
        ulonglong2 ha = hp[0], hb = hp[1];
        a0[0] = ffma2(w0, ha.x, a0[0]); a0[1] = ffma2(w0, ha.y, a0[1]);
        a0[2] = ffma2(w0, hb.x, a0[2]); a0[3] = ffma2(w0, hb.y, a0[3]);
        a1[0] = ffma2(w1, ha.x, a1[0]); a1[1] = ffma2(w1, ha.y, a1[1]);
        a1[2] = ffma2(w1, hb.x, a1[2]); a1[3] = ffma2(w1, hb.y, a1[3]);
    }
    store8(hout + r0 * SPB, a0, bias[r0]);
    store8(hout + r1 * SPB, a1, bias[r1]);
}

// ------------------------------- K1: forward ---------------------------------
__global__ void __launch_bounds__(NT, 4)
fwd_kernel(const float* __restrict__ x,
           const float* __restrict__ b1, const float* __restrict__ b2,
           const float* __restrict__ b3,
           const float* __restrict__ W4, const float* __restrict__ b4,
           int B) {
    extern __shared__ float sm[];
    float* xs   = sm;                   // 64*8
    float* sh1  = xs + DD * SPB;        // 512*8
    float* sh2  = sh1 + HH * SPB;
    float* sh3  = sh2 + HH * SPB;
    float* red2 = sh3 + HH * SPB;       // 16

    const int tid = threadIdx.x, lane = tid & 31, wid = tid >> 5;
    const int b0 = blockIdx.x * SPB;

    for (int t = tid; t < DD * SPB; t += NT) {
        int s = t >> 6, d = t & 63;
        int b = b0 + s;
        xs[d * SPB + s] = (b < B) ? x[(size_t)b * DD + d] : 0.f;
    }
    __syncthreads();

    // layer 1 (via W1T, coalesced)
    {
        int r0 = tid, r1 = tid + NT;
        ull a0[4] = {0, 0, 0, 0}, a1[4] = {0, 0, 0, 0};
#pragma unroll 8
        for (int d = 0; d < DD; d++) {
            ull w0 = dup2(g_W1T[d * HH + r0]);
            ull w1 = dup2(g_W1T[d * HH + r1]);
            const ulonglong2* xp = (const ulonglong2*)(xs + d * SPB);
            ulonglong2 xa = xp[0], xb = xp[1];
            a0[0] = ffma2(w0, xa.x, a0[0]); a0[1] = ffma2(w0, xa.y, a0[1]);
            a0[2] = ffma2(w0, xb.x, a0[2]); a0[3] = ffma2(w0, xb.y, a0[3]);
            a1[0] = ffma2(w1, xa.x, a1[0]); a1[1] = ffma2(w1, xa.y, a1[1]);
            a1[2] = ffma2(w1, xb.x, a1[2]); a1[3] = ffma2(w1, xb.y, a1[3]);
        }
        store8(sh1 + r0 * SPB, a0, b1[r0]);
        store8(sh1 + r1 * SPB, a1, b1[r1]);
    }
    __syncthreads();
    fwd_layer(g_W2T, b2, sh1, sh2, tid);
    __syncthreads();
    fwd_layer(g_W3T, b3, sh2, sh3, tid);
    __syncthreads();

    // s = W4 h3 + b4 ; accumulate 0.5 s^2 (two task passes per thread)
    float sum0 = 0.f, sum1 = 0.f;
#pragma unroll
    for (int pass = 0; pass < 2; pass++) {
        int id = tid + pass * NT;
        int d = id & 63, smp = id >> 6;
        const float4* wrow = (const float4*)(W4 + (size_t)d * HH);
        float acc = 0.f;
#pragma unroll 4
        for (int q = 0; q < HH / 4; q++) {
            float4 w = wrow[q];
            acc = fmaf(w.x, sh3[(4 * q + 0) * SPB + smp], acc);
            acc = fmaf(w.y, sh3[(4 * q + 1) * SPB + smp], acc);
            acc = fmaf(w.z, sh3[(4 * q + 2) * SPB + smp], acc);
            acc = fmaf(w.w, sh3[(4 * q + 3) * SPB + smp], acc);
        }
        float s = acc + b4[d];
        if (pass == 0) sum0 = 0.5f * s * s; else sum1 = 0.5f * s * s;
    }
#pragma unroll
    for (int off = 16; off; off >>= 1) {
        sum0 += __shfl_down_sync(0xffffffffu, sum0, off);
        sum1 += __shfl_down_sync(0xffffffffu, sum1, off);
    }
    if (lane == 0) { red2[wid] = sum0; red2[8 + wid] = sum1; }
    __syncthreads();
    if (tid < SPB && b0 + tid < B) {
        int smp = tid;
        float v = (smp < 4) ? red2[2 * smp] + red2[2 * smp + 1]
                            : red2[8 + 2 * (smp - 4)] + red2[8 + 2 * (smp - 4) + 1];
        g_val0[b0 + smp] = v;
    }

    // deterministic ballot compaction: warp w handles sample w, 3 lists
    if (wid < SPB && b0 + wid < B) {
        int b = b0 + wid;
        const float* hs0 = sh1;
        const float* hs1 = sh2;
        const float* hs2 = sh3;
        for (int l = 0; l < 3; l++) {
            const float* h = (l == 0) ? hs0 : (l == 1) ? hs1 : hs2;
            int* gi = g_idx + ((size_t)l * BMAX + b) * HH;
            int base = 0;
#pragma unroll
            for (int c = 0; c < 16; c++) {
                int e = c * 32 + lane;
                bool f = h[e * SPB + wid] > 0.f;   // h>0 <=> a>0 (strict, torch-style)
                unsigned bal = __ballot_sync(0xffffffffu, f);
                int pos = base + __popc(bal & ((1u << lane) - 1u));
                if (f) gi[pos] = e;
                base += __popc(bal);
            }
            for (int e = base + lane; e < HH; e += 32) gi[e] = 0;  // pad -> zeroed rows
            if (lane == 0) g_cnt[l * BMAX + b] = base;
        }
    }
}

// ------------------------------ K2: divergence --------------------------------
__global__ void __launch_bounds__(NT, 2)
div_kernel(const float* __restrict__ W1, float* __restrict__ out, int B) {
    extern __shared__ float sm[];
    int*   idx1 = (int*)sm;              // 512
    int*   idx2 = idx1 + HH;
    int*   idx3 = idx2 + HH;
    float* red  = (float*)(idx3 + HH);   // 8
    float* smA  = red + 8;               // 512*20 (byte offset 6176, 16B aligned)
    float* smB  = smA + HH * BROW;

    const int tid = threadIdx.x;
    const int b = blockIdx.x;

    const int n1 = g_cnt[b], n2 = g_cnt[BMAX + b], n3 = g_cnt[2 * BMAX + b];
    for (int e = tid; e < HH; e += NT) {
        idx1[e] = g_idx[(size_t)b * HH + e];
        idx2[e] = g_idx[((size_t)BMAX + b) * HH + e];
        idx3[e] = g_idx[((size_t)2 * BMAX + b) * HH + e];
    }
    __syncthreads();

    const int n1p = (n1 + 3) & ~3;
    const int n2p = (n2 + 3) & ~3;
    float div_acc = 0.f;

#pragma unroll 1
    for (int d0 = 0; d0 < DD; d0 += DB) {
        // stage smA[ic][0..15] = W1[idx1[ic]][d0..d0+15]; zero pad rows
        for (int ic = tid; ic < n1p; ic += NT) {
            float4 v0, v1, v2, v3;
            if (ic < n1) {
                const float4* src = (const float4*)(W1 + (size_t)idx1[ic] * DD + d0);
                v0 = src[0]; v1 = src[1]; v2 = src[2]; v3 = src[3];
            } else {
                v0 = v1 = v2 = v3 = make_float4(0.f, 0.f, 0.f, 0.f);
            }
            float4* dst = (float4*)(smA + ic * BROW);
            dst[0] = v0; dst[1] = v1; dst[2] = v2; dst[3] = v3;
        }
        __syncthreads();

        // GEMM1: smB[jc] = sum_ic W2[idx2[jc], idx1[ic]] * smA[ic]
        for (int jc = tid; jc < n2p; jc += NT) {
            float4 o0, o1, o2, o3;
            if (jc < n2) {
                const float* wcol = g_W2T + idx2[jc];
                ull acc[8];
#pragma unroll
                for (int q = 0; q < 8; q++) acc[q] = 0ull;
#pragma unroll 4
                for (int ic = 0; ic < n1p; ic++) {
                    ull wd = dup2(wcol[(size_t)idx1[ic] * HH]);
                    const ulonglong2* br = (const ulonglong2*)(smA + ic * BROW);
                    ulonglong2 u0 = br[0], u1 = br[1], u2 = br[2], u3 = br[3];
                    acc[0] = ffma2(wd, u0.x, acc[0]); acc[1] = ffma2(wd, u0.y, acc[1]);
                    acc[2] = ffma2(wd, u1.x, acc[2]); acc[3] = ffma2(wd, u1.y, acc[3]);
                    acc[4] = ffma2(wd, u2.x, acc[4]); acc[5] = ffma2(wd, u2.y, acc[5]);
                    acc[6] = ffma2(wd, u3.x, acc[6]); acc[7] = ffma2(wd, u3.y, acc[7]);
                }
                float2 p0 = unpack2(acc[0]), p1 = unpack2(acc[1]);
                float2 p2 = unpack2(acc[2]), p3 = unpack2(acc[3]);
                float2 p4 = unpack2(acc[4]), p5 = unpack2(acc[5]);
                float2 p6 = unpack2(acc[6]), p7 = unpack2(acc[7]);
                o0 = make_float4(p0.x, p0.y, p1.x, p1.y);
                o1 = make_float4(p2.x, p2.y, p3.x, p3.y);
                o2 = make_float4(p4.x, p4.y, p5.x, p5.y);
                o3 = make_float4(p6.x, p6.y, p7.x, p7.y);
            } else {
                o0 = o1 = o2 = o3 = make_float4(0.f, 0.f, 0.f, 0.f);
            }
            float4* dst = (float4*)(smB + jc * BROW);
            dst[0] = o0; dst[1] = o1; dst[2] = o2; dst[3] = o3;
        }
        __syncthreads();

        // GEMM2 + fold: for active k rows, dot (W3 @ smB)[k] with W4T[k, d0..]
        for (int kc = tid; kc < n3; kc += NT) {
            int k = idx3[kc];
            const float* wcol = g_W3T + k;
            ull acc[8];
#pragma unroll
            for (int q = 0; q < 8; q++) acc[q] = 0ull;
#pragma unroll 4
            for (int jc = 0; jc < n2p; jc++) {
                ull wd = dup2(wcol[(size_t)idx2[jc] * HH]);
                const ulonglong2* br = (const ulonglong2*)(smB + jc * BROW);
                ulonglong2 u0 = br[0], u1 = br[1], u2 = br[2], u3 = br[3];
                acc[0] = ffma2(wd, u0.x, acc[0]); acc[1] = ffma2(wd, u0.y, acc[1]);
                acc[2] = ffma2(wd, u1.x, acc[2]); acc[3] = ffma2(wd, u1.y, acc[3]);
                acc[4] = ffma2(wd, u2.x, acc[4]); acc[5] = ffma2(wd, u2.y, acc[5]);
                acc[6] = ffma2(wd, u3.x, acc[6]); acc[7] = ffma2(wd, u3.y, acc[7]);
            }
            const float4* w4 = (const float4*)(g_W4T + (size_t)k * DD + d0);
            float4 wa = w4[0], wb = w4[1], wc = w4[2], wd4 = w4[3];
            float2 p0 = unpack2(acc[0]), p1 = unpack2(acc[1]);
            float2 p2 = unpack2(acc[2]), p3 = unpack2(acc[3]);
            float2 p4 = unpack2(acc[4]), p5 = unpack2(acc[5]);
            float2 p6 = unpack2(acc[6]), p7 = unpack2(acc[7]);
            div_acc += p0.x * wa.x + p0.y * wa.y + p1.x * wa.z + p1.y * wa.w
                     + p2.x * wb.x + p2.y * wb.y + p3.x * wb.z + p3.y * wb.w
                     + p4.x * wc.x + p4.y * wc.y + p5.x * wc.z + p5.y * wc.w
                     + p6.x * wd4.x + p6.y * wd4.y + p7.x * wd4.z + p7.y * wd4.w;
        }
        __syncthreads();
    }

    float v = div_acc;
#pragma unroll
    for (int off = 16; off; off >>= 1) v += __shfl_down_sync(0xffffffffu, v, off);
    if ((tid & 31) == 0) red[tid >> 5] = v;
    __syncthreads();
    if (tid == 0) {
        float t = g_val0[b];
#pragma unroll
        for (int w = 0; w < NT / 32; w++) t += red[w];
        out[b] = t;
    }
}

// ------------------------------- launcher -----------------------------------
extern "C" void kernel_launch(void* const* d_in, const int* in_sizes, int n_in,
                              void* d_out, int out_size) {
    const float* x  = (const float*)d_in[0];
    const float* W1 = (const float*)d_in[1];
    const float* b1 = (const float*)d_in[2];
    const float* W2 = (const float*)d_in[3];
    const float* b2 = (const float*)d_in[4];
    const float* W3 = (const float*)d_in[5];
    const float* b3 = (const float*)d_in[6];
    const float* W4 = (const float*)d_in[7];
    const float* b4 = (const float*)d_in[8];
    float* out = (float*)d_out;

    int B = in_sizes[0] / DD;

    prep_transpose<<<dim3(16, 16, 4), dim3(32, 8)>>>(W1, W2, W3, W4);

    size_t sm1 = (size_t)(DD * SPB + 3 * HH * SPB + 16) * sizeof(float);
    cudaFuncSetAttribute(fwd_kernel, cudaFuncAttributeMaxDynamicSharedMemorySize, (int)sm1);
    fwd_kernel<<<(B + SPB - 1) / SPB, NT, sm1>>>(x, b1, b2, b3, W4, b4, B);

    size_t sm2 = (size_t)(3 * HH) * sizeof(int) + (size_t)(8 + 2 * HH * BROW) * sizeof(float);
    cudaFuncSetAttribute(div_kernel, cudaFuncAttributeMaxDynamicSharedMemorySize, (int)sm2);
    div_kernel<<<B, NT, sm2>>>(W1, out, B);
}

// round 12
// speedup vs baseline: 1.0051x; 1.0014x over previous
#include <cuda_runtime.h>
#include <cstdint>

// ScoreMatching, sparsity-compacted version.
//  K0 prep: transpose W1,W2,W3,W4 into __device__ scratch (coalesced columns)
//  K1 fwd : 8 samples/CTA, computes h/masks, 0.5||s||^2 -> g_val0,
//           and deterministic ballot-compacted active index lists -> g_idx/g_cnt
//  K2 div : 1 sample/CTA, compacted GEMM chain over active units only:
//           smA = W1[idx1,:] slice ; smB = W2[idx2, idx1] @ smA ;
//           div += sum over idx3 rows of (W3 @ smB) . W4T  (T2 never stored)
//  fp32 throughout, fma.rn.f32x2 packed FMA (128 MAC/cyc/SM).

#define DD   64
#define HH   512
#define DB   16
#define BROW 20          // 16 + 4 pad floats (16B-aligned rows, conflict-poor STS.128)
#define NT   256
#define SPB  8           // samples per forward CTA
#define BMAX 4096

typedef unsigned long long ull;

__device__ float g_W1T[DD * HH];   // W1T[d*512 + i] = W1[i][d]
__device__ float g_W2T[HH * HH];   // W2T[i*512 + j] = W2[j][i]
__device__ float g_W3T[HH * HH];   // W3T[j*512 + k] = W3[k][j]
__device__ float g_W4T[HH * DD];   // W4T[k*64  + d] = W4[d][k]
__device__ float g_val0[BMAX];     // 0.5*||s_b||^2
__device__ int   g_idx[3 * BMAX * HH];
__device__ int   g_cnt[3 * BMAX];

__device__ __forceinline__ ull ffma2(ull a, ull b, ull c) {
    ull d;
    asm("fma.rn.f32x2 %0, %1, %2, %3;" : "=l"(d) : "l"(a), "l"(b), "l"(c));
    return d;
}
__device__ __forceinline__ ull dup2(float w) {
    ull r;
    unsigned int u = __float_as_uint(w);
    asm("mov.b64 %0, {%1, %1};" : "=l"(r) : "r"(u));
    return r;
}
__device__ __forceinline__ float2 unpack2(ull v) {
    unsigned int lo, hi;
    asm("mov.b64 {%0, %1}, %2;" : "=r"(lo), "=r"(hi) : "l"(v));
    return make_float2(__uint_as_float(lo), __uint_as_float(hi));
}

// -------- prep: tiled transposes into __device__ scratch --------
__global__ void prep_transpose(const float* __restrict__ W1,
                               const float* __restrict__ W2,
                               const float* __restrict__ W3,
                               const float* __restrict__ W4) {
    __shared__ float tile[32][33];
    int z = blockIdx.z;
    const float* src = (z == 0) ? W2 : (z == 1) ? W3 : (z == 2) ? W4 : W1;
    float* dst       = (z == 0) ? g_W2T : (z == 1) ? g_W3T : (z == 2) ? g_W4T : g_W1T;
    int R = (z == 2) ? DD : HH;       // source rows
    int C = (z == 3) ? DD : HH;       // source cols
    int c0 = blockIdx.x * 32, r0 = blockIdx.y * 32;
    if (c0 >= C || r0 >= R) return;
    int tx = threadIdx.x, ty = threadIdx.y;
#pragma unroll
    for (int j = ty; j < 32; j += 8)
        tile[j][tx] = src[(size_t)(r0 + j) * C + c0 + tx];
    __syncthreads();
#pragma unroll
    for (int j = ty; j < 32; j += 8)
        dst[(size_t)(c0 + j) * R + r0 + tx] = tile[tx][j];
}

// relu + bias epilogue: 4 packed accumulators -> 8 floats at dst[0..7]
__device__ __forceinline__ void store8(float* dst, const ull* a, float bb) {
#pragma unroll
    for (int q = 0; q < 4; q++) {
        float2 p = unpack2(a[q]);
        float v0 = p.x + bb, v1 = p.y + bb;
        dst[2 * q]     = v0 > 0.f ? v0 : 0.f;
        dst[2 * q + 1] = v1 > 0.f ? v1 : 0.f;
    }
}

// one hidden layer for 8 samples: rows (tid, tid+256), hin layout [k*8+s]
__device__ __forceinline__ void fwd_layer(const float* __restrict__ WT,
                                          const float* __restrict__ bias,
                                          const float* __restrict__ hin,
                                          float* __restrict__ hout, int tid) {
    int r0 = tid, r1 = tid + NT;
    ull a0[4] = {0, 0, 0, 0}, a1[4] = {0, 0, 0, 0};
#pragma unroll 4
    for (int k = 0; k < HH; k++) {
        ull w0 = dup2(WT[(size_t)k * HH + r0]);
        ull w1 = dup2(WT[(size_t)k * HH + r1]);
        const ulonglong2* hp = (const ulonglong2*)(hin + k * SPB);
        ulonglong2 ha = hp[0], hb = hp[1];
        a0[0] = ffma2(w0, ha.x, a0[0]); a0[1] = ffma2(w0, ha.y, a0[1]);
        a0[2] = ffma2(w0, hb.x, a0[2]); a0[3] = ffma2(w0, hb.y, a0[3]);
        a1[0] = ffma2(w1, ha.x, a1[0]); a1[1] = ffma2(w1, ha.y, a1[1]);
        a1[2] = ffma2(w1, hb.x, a1[2]); a1[3] = ffma2(w1, hb.y, a1[3]);
    }
    store8(hout + r0 * SPB, a0, bias[r0]);
    store8(hout + r1 * SPB, a1, bias[r1]);
}

// ------------------------------- K1: forward ---------------------------------
__global__ void __launch_bounds__(NT, 4)
fwd_kernel(const float* __restrict__ x,
           const float* __restrict__ b1, const float* __restrict__ b2,
           const float* __restrict__ b3,
           const float* __restrict__ W4, const float* __restrict__ b4,
           int B) {
    extern __shared__ float sm[];
    float* xs   = sm;                   // 64*8
    float* sh1  = xs + DD * SPB;        // 512*8
    float* sh2  = sh1 + HH * SPB;
    float* sh3  = sh2 + HH * SPB;
    float* red2 = sh3 + HH * SPB;       // 16

    const int tid = threadIdx.x, lane = tid & 31, wid = tid >> 5;
    const int b0 = blockIdx.x * SPB;

    for (int t = tid; t < DD * SPB; t += NT) {
        int s = t >> 6, d = t & 63;
        int b = b0 + s;
        xs[d * SPB + s] = (b < B) ? x[(size_t)b * DD + d] : 0.f;
    }
    __syncthreads();

    // layer 1 (via W1T, coalesced)
    {
        int r0 = tid, r1 = tid + NT;
        ull a0[4] = {0, 0, 0, 0}, a1[4] = {0, 0, 0, 0};
#pragma unroll 8
        for (int d = 0; d < DD; d++) {
            ull w0 = dup2(g_W1T[d * HH + r0]);
            ull w1 = dup2(g_W1T[d * HH + r1]);
            const ulonglong2* xp = (const ulonglong2*)(xs + d * SPB);
            ulonglong2 xa = xp[0], xb = xp[1];
            a0[0] = ffma2(w0, xa.x, a0[0]); a0[1] = ffma2(w0, xa.y, a0[1]);
            a0[2] = ffma2(w0, xb.x, a0[2]); a0[3] = ffma2(w0, xb.y, a0[3]);
            a1[0] = ffma2(w1, xa.x, a1[0]); a1[1] = ffma2(w1, xa.y, a1[1]);
            a1[2] = ffma2(w1, xb.x, a1[2]); a1[3] = ffma2(w1, xb.y, a1[3]);
        }
        store8(sh1 + r0 * SPB, a0, b1[r0]);
        store8(sh1 + r1 * SPB, a1, b1[r1]);
    }
    __syncthreads();
    fwd_layer(g_W2T, b2, sh1, sh2, tid);
    __syncthreads();
    fwd_layer(g_W3T, b3, sh2, sh3, tid);
    __syncthreads();

    // s = W4 h3 + b4 ; accumulate 0.5 s^2 (two task passes per thread)
    float sum0 = 0.f, sum1 = 0.f;
#pragma unroll
    for (int pass = 0; pass < 2; pass++) {
        int id = tid + pass * NT;
        int d = id & 63, smp = id >> 6;
        const float4* wrow = (const float4*)(W4 + (size_t)d * HH);
        float acc = 0.f;
#pragma unroll 4
        for (int q = 0; q < HH / 4; q++) {
            float4 w = wrow[q];
            acc = fmaf(w.x, sh3[(4 * q + 0) * SPB + smp], acc);
            acc = fmaf(w.y, sh3[(4 * q + 1) * SPB + smp], acc);
            acc = fmaf(w.z, sh3[(4 * q + 2) * SPB + smp], acc);
            acc = fmaf(w.w, sh3[(4 * q + 3) * SPB + smp], acc);
        }
        float s = acc + b4[d];
        if (pass == 0) sum0 = 0.5f * s * s; else sum1 = 0.5f * s * s;
    }
#pragma unroll
    for (int off = 16; off; off >>= 1) {
        sum0 += __shfl_down_sync(0xffffffffu, sum0, off);
        sum1 += __shfl_down_sync(0xffffffffu, sum1, off);
    }
    if (lane == 0) { red2[wid] = sum0; red2[8 + wid] = sum1; }
    __syncthreads();
    if (tid < SPB && b0 + tid < B) {
        int smp = tid;
        float v = (smp < 4) ? red2[2 * smp] + red2[2 * smp + 1]
                            : red2[8 + 2 * (smp - 4)] + red2[8 + 2 * (smp - 4) + 1];
        g_val0[b0 + smp] = v;
    }

    // deterministic ballot compaction: warp w handles sample w, 3 lists
    if (wid < SPB && b0 + wid < B) {
        int b = b0 + wid;
        const float* hs0 = sh1;
        const float* hs1 = sh2;
        const float* hs2 = sh3;
        for (int l = 0; l < 3; l++) {
            const float* h = (l == 0) ? hs0 : (l == 1) ? hs1 : hs2;
            int* gi = g_idx + ((size_t)l * BMAX + b) * HH;
            int base = 0;
#pragma unroll
            for (int c = 0; c < 16; c++) {
                int e = c * 32 + lane;
                bool f = h[e * SPB + wid] > 0.f;   // h>0 <=> a>0 (strict, torch-style)
                unsigned bal = __ballot_sync(0xffffffffu, f);
                int pos = base + __popc(bal & ((1u << lane) - 1u));
                if (f) gi[pos] = e;
                base += __popc(bal);
            }
            for (int e = base + lane; e < HH; e += 32) gi[e] = 0;  // pad -> zeroed rows
            if (lane == 0) g_cnt[l * BMAX + b] = base;
        }
    }
}

// ------------------------------ K2: divergence --------------------------------
__global__ void __launch_bounds__(NT, 2)
div_kernel(const float* __restrict__ W1, float* __restrict__ out, int B) {
    extern __shared__ float sm[];
    int*   idx1 = (int*)sm;              // 512
    int*   idx2 = idx1 + HH;
    int*   idx3 = idx2 + HH;
    float* red  = (float*)(idx3 + HH);   // 8
    float* smA  = red + 8;               // 512*20 (byte offset 6176, 16B aligned)
    float* smB  = smA + HH * BROW;

    const int tid = threadIdx.x;
    const int b = blockIdx.x;

    const int n1 = g_cnt[b], n2 = g_cnt[BMAX + b], n3 = g_cnt[2 * BMAX + b];
    for (int e = tid; e < HH; e += NT) {
        idx1[e] = g_idx[(size_t)b * HH + e];
        idx2[e] = g_idx[((size_t)BMAX + b) * HH + e];
        idx3[e] = g_idx[((size_t)2 * BMAX + b) * HH + e];
    }
    __syncthreads();

    const int n1p = (n1 + 3) & ~3;
    const int n2p = (n2 + 3) & ~3;
    float div_acc = 0.f;

#pragma unroll 1
    for (int d0 = 0; d0 < DD; d0 += DB) {
        // stage smA[ic][0..15] = W1[idx1[ic]][d0..d0+15]; zero pad rows
        for (int ic = tid; ic < n1p; ic += NT) {
            float4 v0, v1, v2, v3;
            if (ic < n1) {
                const float4* src = (const float4*)(W1 + (size_t)idx1[ic] * DD + d0);
                v0 = src[0]; v1 = src[1]; v2 = src[2]; v3 = src[3];
            } else {
                v0 = v1 = v2 = v3 = make_float4(0.f, 0.f, 0.f, 0.f);
            }
            float4* dst = (float4*)(smA + ic * BROW);
            dst[0] = v0; dst[1] = v1; dst[2] = v2; dst[3] = v3;
        }
        __syncthreads();

        // GEMM1: smB[jc] = sum_ic W2[idx2[jc], idx1[ic]] * smA[ic]
        for (int jc = tid; jc < n2p; jc += NT) {
            float4 o0, o1, o2, o3;
            if (jc < n2) {
                const float* wcol = g_W2T + idx2[jc];
                ull acc[8];
#pragma unroll
                for (int q = 0; q < 8; q++) acc[q] = 0ull;
#pragma unroll 4
                for (int ic = 0; ic < n1p; ic++) {
                    ull wd = dup2(wcol[(size_t)idx1[ic] * HH]);
                    const ulonglong2* br = (const ulonglong2*)(smA + ic * BROW);
                    ulonglong2 u0 = br[0], u1 = br[1], u2 = br[2], u3 = br[3];
                    acc[0] = ffma2(wd, u0.x, acc[0]); acc[1] = ffma2(wd, u0.y, acc[1]);
                    acc[2] = ffma2(wd, u1.x, acc[2]); acc[3] = ffma2(wd, u1.y, acc[3]);
                    acc[4] = ffma2(wd, u2.x, acc[4]); acc[5] = ffma2(wd, u2.y, acc[5]);
                    acc[6] = ffma2(wd, u3.x, acc[6]); acc[7] = ffma2(wd, u3.y, acc[7]);
                }
                float2 p0 = unpack2(acc[0]), p1 = unpack2(acc[1]);
                float2 p2 = unpack2(acc[2]), p3 = unpack2(acc[3]);
                float2 p4 = unpack2(acc[4]), p5 = unpack2(acc[5]);
                float2 p6 = unpack2(acc[6]), p7 = unpack2(acc[7]);
                o0 = make_float4(p0.x, p0.y, p1.x, p1.y);
                o1 = make_float4(p2.x, p2.y, p3.x, p3.y);
                o2 = make_float4(p4.x, p4.y, p5.x, p5.y);
                o3 = make_float4(p6.x, p6.y, p7.x, p7.y);
            } else {
                o0 = o1 = o2 = o3 = make_float4(0.f, 0.f, 0.f, 0.f);
            }
            float4* dst = (float4*)(smB + jc * BROW);
            dst[0] = o0; dst[1] = o1; dst[2] = o2; dst[3] = o3;
        }
        __syncthreads();

        // GEMM2 + fold: for active k rows, dot (W3 @ smB)[k] with W4T[k, d0..]
        for (int kc = tid; kc < n3; kc += NT) {
            int k = idx3[kc];
            const float* wcol = g_W3T + k;
            ull acc[8];
#pragma unroll
            for (int q = 0; q < 8; q++) acc[q] = 0ull;
#pragma unroll 4
            for (int jc = 0; jc < n2p; jc++) {
                ull wd = dup2(wcol[(size_t)idx2[jc] * HH]);
                const ulonglong2* br = (const ulonglong2*)(smB + jc * BROW);
                ulonglong2 u0 = br[0], u1 = br[1], u2 = br[2], u3 = br[3];
                acc[0] = ffma2(wd, u0.x, acc[0]); acc[1] = ffma2(wd, u0.y, acc[1]);
                acc[2] = ffma2(wd, u1.x, acc[2]); acc[3] = ffma2(wd, u1.y, acc[3]);
                acc[4] = ffma2(wd, u2.x, acc[4]); acc[5] = ffma2(wd, u2.y, acc[5]);
                acc[6] = ffma2(wd, u3.x, acc[6]); acc[7] = ffma2(wd, u3.y, acc[7]);
            }
            const float4* w4 = (const float4*)(g_W4T + (size_t)k * DD + d0);
            float4 wa = w4[0], wb = w4[1], wc = w4[2], wd4 = w4[3];
            float2 p0 = unpack2(acc[0]), p1 = unpack2(acc[1]);
            float2 p2 = unpack2(acc[2]), p3 = unpack2(acc[3]);
            float2 p4 = unpack2(acc[4]), p5 = unpack2(acc[5]);
            float2 p6 = unpack2(acc[6]), p7 = unpack2(acc[7]);
            div_acc += p0.x * wa.x + p0.y * wa.y + p1.x * wa.z + p1.y * wa.w
                     + p2.x * wb.x + p2.y * wb.y + p3.x * wb.z + p3.y * wb.w
                     + p4.x * wc.x + p4.y * wc.y + p5.x * wc.z + p5.y * wc.w
                     + p6.x * wd4.x + p6.y * wd4.y + p7.x * wd4.z + p7.y * wd4.w;
        }
        __syncthreads();
    }

    float v = div_acc;
#pragma unroll
    for (int off = 16; off; off >>= 1) v += __shfl_down_sync(0xffffffffu, v, off);
    if ((tid & 31) == 0) red[tid >> 5] = v;
    __syncthreads();
    if (tid == 0) {
        float t = g_val0[b];
#pragma unroll
        for (int w = 0; w < NT / 32; w++) t += red[w];
        out[b] = t;
    }
}

// ------------------------------- launcher -----------------------------------
extern "C" void kernel_launch(void* const* d_in, const int* in_sizes, int n_in,
                              void* d_out, int out_size) {
    const float* x  = (const float*)d_in[0];
    const float* W1 = (const float*)d_in[1];
    const float* b1 = (const float*)d_in[2];
    const float* W2 = (const float*)d_in[3];
    const float* b2 = (const float*)d_in[4];
    const float* W3 = (const float*)d_in[5];
    const float* b3 = (const float*)d_in[6];
    const float* W4 = (const float*)d_in[7];
    const float* b4 = (const float*)d_in[8];
    float* out = (float*)d_out;

    int B = in_sizes[0] / DD;

    prep_transpose<<<dim3(16, 16, 4), dim3(32, 8)>>>(W1, W2, W3, W4);

    size_t sm1 = (size_t)(DD * SPB + 3 * HH * SPB + 16) * sizeof(float);
    cudaFuncSetAttribute(fwd_kernel, cudaFuncAttributeMaxDynamicSharedMemorySize, (int)sm1);
    fwd_kernel<<<(B + SPB - 1) / SPB, NT, sm1>>>(x, b1, b2, b3, W4, b4, B);

    size_t sm2 = (size_t)(3 * HH) * sizeof(int) + (size_t)(8 + 2 * HH * BROW) * sizeof(float);
    cudaFuncSetAttribute(div_kernel, cudaFuncAttributeMaxDynamicSharedMemorySize, (int)sm2);
    div_kernel<<<B, NT, sm2>>>(W1, out, B);
}